// round 10
// baseline (speedup 1.0000x reference)
#include <cuda_runtime.h>
#include <cstdint>

// Problem constants
#define BH_  64
#define S_   1024
#define D_   64
#define QT   16      // queries per CTA (2 CTAs/SM)
#define KC   128     // keys per chunk
#define NCH  (S_/KC) // 8
#define NTHREADS 512

// smem strides (floats)
#define PADK 68      // K/Q rows: QK B-loads conflict-free
#define PADV 72      // V rows:   PV B-loads conflict-free
#define PADS 1028    // score rows: PV A-loads conflict-free
#define RSTR 36      // reduction partial row stride
#define RPART 578    // floats per partial tile (16*36 + 2)

// smem layout (float offsets)
#define OFF_Q    0
#define SZ_Q     (QT*PADK)          // 1088
#define OFF_KV   (OFF_Q + SZ_Q)
#define SZ_KV    (KC*PADV)          // 9216 (single buffer)
#define OFF_S    (OFF_KV + SZ_KV)
#define SZ_S     (QT*PADS)          // 16448 (reused for 16*RPART=9248 reduction)
#define OFF_MAXP (OFF_S + SZ_S)     // 16 rows x 16 warps
#define OFF_M    (OFF_MAXP + 256)   // mask: 1024 ints
#define OFF_INV  (OFF_M + S_)       // 16 floats
#define SMEM_FLOATS (OFF_INV + 16)
#define SMEM_BYTES  (SMEM_FLOATS * 4)   // 112,192 B -> 2 CTAs/SM

#define NEGB (-1e30f)

__device__ __forceinline__ unsigned f2tf(float x) {
    unsigned r;
    asm("cvt.rna.tf32.f32 %0, %1;" : "=r"(r) : "f"(x));
    return r;
}

__device__ __forceinline__ void mma8(float* c, const unsigned* a, unsigned b0, unsigned b1) {
    asm volatile(
        "mma.sync.aligned.m16n8k8.row.col.f32.tf32.tf32.f32 "
        "{%0,%1,%2,%3},{%4,%5,%6,%7},{%8,%9},{%0,%1,%2,%3};\n"
        : "+f"(c[0]), "+f"(c[1]), "+f"(c[2]), "+f"(c[3])
        : "r"(a[0]), "r"(a[1]), "r"(a[2]), "r"(a[3]), "r"(b0), "r"(b1));
}

__device__ __forceinline__ void cpasync16(float* smem_dst, const float* gsrc) {
    unsigned d = (unsigned)__cvta_generic_to_shared(smem_dst);
    asm volatile("cp.async.cg.shared.global [%0],[%1],16;\n" :: "r"(d), "l"(gsrc));
}
#define CP_COMMIT() asm volatile("cp.async.commit_group;\n" ::: "memory")
#define CP_WAIT0()  asm volatile("cp.async.wait_group 0;\n" ::: "memory")

__global__ void __launch_bounds__(NTHREADS, 2)
attn_kernel(const float* __restrict__ Q, const float* __restrict__ K,
            const float* __restrict__ V, const int* __restrict__ M,
            float* __restrict__ Out, float* __restrict__ Attn)
{
    extern __shared__ float sm[];
    float* sQ    = sm + OFF_Q;
    float* sKV   = sm + OFF_KV;   // single buffer (K layout PADK / V layout PADV)
    float* sS    = sm + OFF_S;    // 16 x 1024 scores/probs; later reduction scratch
    float* sMaxP = sm + OFF_MAXP; // [row][warp] partial maxes
    int*   sM    = (int*)(sm + OFF_M);
    float* sInv  = sm + OFF_INV;

    const int bh   = blockIdx.y;
    const int q0   = blockIdx.x * QT;
    const int tid  = threadIdx.x;
    const int lane = tid & 31;
    const int warp = tid >> 5;   // 0..15

    const float* gQ = Q + ((size_t)bh * S_ + q0) * D_;
    const float* gK = K + (size_t)bh * S_ * D_;
    const float* gV = V + (size_t)bh * S_ * D_;
    const int*   gM = M + bh * S_;
    float* gO = Out + ((size_t)bh * S_ + q0) * D_;
    float* gA = Attn ? (Attn + ((size_t)bh * S_ + q0) * S_) : nullptr;

    // ---- issue K chunk 0, stage Q + mask ----
    #pragma unroll
    for (int j = 0; j < 4; j++) {           // 128 rows x 16 f4 = 2048 f4 / 512 thr
        int f = j * NTHREADS + tid;
        int row = f >> 4, c4 = f & 15;
        cpasync16(sKV + row * PADK + c4 * 4, gK + row * D_ + c4 * 4);
    }
    CP_COMMIT();
    if (tid < 256) {                        // Q: 16 rows x 16 f4
        int row = tid >> 4, c4 = tid & 15;
        float4 val = reinterpret_cast<const float4*>(gQ)[row * (D_ / 4) + c4];
        *reinterpret_cast<float4*>(sQ + row * PADK + c4 * 4) = val;
    } else {                                // mask: 256 int4
        int i = tid - 256;
        reinterpret_cast<int4*>(sM)[i] = reinterpret_cast<const int4*>(gM)[i];
    }
    CP_WAIT0();
    __syncthreads();   // K0, sQ, sM visible

    // ---- Q (A) fragments in tf32, persistent ----
    unsigned afr[8][4];
    #pragma unroll
    for (int ks = 0; ks < 8; ks++) {
        int r0 = lane >> 2;
        int c0 = (lane & 3) + ks * 8;
        afr[ks][0] = f2tf(sQ[r0 * PADK + c0]);
        afr[ks][1] = f2tf(sQ[(r0 + 8) * PADK + c0]);
        afr[ks][2] = f2tf(sQ[r0 * PADK + c0 + 4]);
        afr[ks][3] = f2tf(sQ[(r0 + 8) * PADK + c0 + 4]);
    }

    // ---- QK^T: 16 warps x n8, single KV buffer; running row-max in regs ----
    const int wn = warp;     // keys wn*8 .. wn*8+7 of each chunk
    float mlo = NEGB, mhi = NEGB;
    for (int c = 0; c < NCH; c++) {
        const float* sK = sKV;
        float acc[4] = {0.f, 0.f, 0.f, 0.f};
        #pragma unroll
        for (int ks = 0; ks < 8; ks++) {
            int key = wn * 8 + (lane >> 2);
            int d0  = (lane & 3) + ks * 8;
            unsigned b0 = f2tf(sK[key * PADK + d0]);
            unsigned b1 = f2tf(sK[key * PADK + d0 + 4]);
            mma8(acc, afr[ks], b0, b1);
        }
        __syncthreads();    // all warps done reading K(c)
        if (c + 1 < NCH) {  // issue K(c+1)
            const float* src = gK + (size_t)(c + 1) * KC * D_;
            #pragma unroll
            for (int j = 0; j < 4; j++) {
                int f = j * NTHREADS + tid;
                int row = f >> 4, c4 = f & 15;
                cpasync16(sKV + row * PADK + c4 * 4, src + row * D_ + c4 * 4);
            }
        } else {            // issue V0 (PADV layout)
            #pragma unroll
            for (int j = 0; j < 4; j++) {
                int f = j * NTHREADS + tid;
                int row = f >> 4, c4 = f & 15;
                cpasync16(sKV + row * PADV + c4 * 4, gV + row * D_ + c4 * 4);
            }
        }
        CP_COMMIT();
        // scores + mask + running max (overlaps the in-flight load)
        {
            int col = c * KC + wn * 8 + 2 * (lane & 3);
            int r0  = lane >> 2;
            int2 mk = *reinterpret_cast<const int2*>(&sM[col]);
            float s0 = mk.x ? acc[0] : NEGB;
            float s1 = mk.y ? acc[1] : NEGB;
            float s2 = mk.x ? acc[2] : NEGB;
            float s3 = mk.y ? acc[3] : NEGB;
            *reinterpret_cast<float2*>(&sS[r0 * PADS + col])       = make_float2(s0, s1);
            *reinterpret_cast<float2*>(&sS[(r0 + 8) * PADS + col]) = make_float2(s2, s3);
            mlo = fmaxf(mlo, fmaxf(s0, s1));
            mhi = fmaxf(mhi, fmaxf(s2, s3));
        }
        if (c + 1 < NCH) { CP_WAIT0(); __syncthreads(); }
    }
    // quad-reduce running maxes, publish per-warp partials
    mlo = fmaxf(mlo, __shfl_xor_sync(0xffffffffu, mlo, 1));
    mlo = fmaxf(mlo, __shfl_xor_sync(0xffffffffu, mlo, 2));
    mhi = fmaxf(mhi, __shfl_xor_sync(0xffffffffu, mhi, 1));
    mhi = fmaxf(mhi, __shfl_xor_sync(0xffffffffu, mhi, 2));
    if ((lane & 3) == 0) {
        sMaxP[(lane >> 2) * 16 + wn]       = mlo;
        sMaxP[((lane >> 2) + 8) * 16 + wn] = mhi;
    }
    CP_WAIT0();
    __syncthreads();   // V0 ready; scores + sMaxP visible

    // ---- softmax: warp r owns row r (32 lanes, 8 f4 each) ----
    {
        const int r = warp;
        const float CEXP = 0.125f * 1.44269504088896340736f;  // (1/T)*log2(e)
        // BUGFIX (R9 NaN): both 16-lane halves load the same partials, so the
        // xor-1/2/4/8 butterfly yields the true row max in ALL 32 lanes.
        float m = sMaxP[r * 16 + (lane & 15)];
        m = fmaxf(m, __shfl_xor_sync(0xffffffffu, m, 1));
        m = fmaxf(m, __shfl_xor_sync(0xffffffffu, m, 2));
        m = fmaxf(m, __shfl_xor_sync(0xffffffffu, m, 4));
        m = fmaxf(m, __shfl_xor_sync(0xffffffffu, m, 8));

        float4* rowS = reinterpret_cast<float4*>(sS + (size_t)r * PADS);
        float l = 0.f;
        #pragma unroll
        for (int j = 0; j < 8; j++) {
            int i4 = lane + j * 32;
            float4 s = rowS[i4];
            float4 p;
            p.x = exp2f((s.x - m) * CEXP);
            p.y = exp2f((s.y - m) * CEXP);
            p.z = exp2f((s.z - m) * CEXP);
            p.w = exp2f((s.w - m) * CEXP);
            rowS[i4] = p;              // unnormalized p kept for PV
            l += (p.x + p.y) + (p.z + p.w);
        }
        l += __shfl_xor_sync(0xffffffffu, l, 1);
        l += __shfl_xor_sync(0xffffffffu, l, 2);
        l += __shfl_xor_sync(0xffffffffu, l, 4);
        l += __shfl_xor_sync(0xffffffffu, l, 8);
        l += __shfl_xor_sync(0xffffffffu, l, 16);
        if (lane == 0) sInv[r] = 1.f / l;   // l >= 1 always
    }
    __syncthreads();   // probs + sInv visible

    // ---- P(unnorm) @ V: 8k x 2n split; attn write folded into the loop ----
    const int wk  = warp & 7;    // keys wk*16..+15 within chunk
    const int wnv = warp >> 3;   // cols wnv*32..+31
    float o[4][4];
    #pragma unroll
    for (int nt = 0; nt < 4; nt++) { o[nt][0] = o[nt][1] = o[nt][2] = o[nt][3] = 0.f; }

    for (int c = 0; c < NCH; c++) {
        const float* sV = sKV;
        #pragma unroll
        for (int kk = 0; kk < 2; kk++) {
            unsigned a[4];
            int r0 = lane >> 2;
            int kc = c * KC + wk * 16 + kk * 8 + (lane & 3);
            a[0] = f2tf(sS[r0 * PADS + kc]);
            a[1] = f2tf(sS[(r0 + 8) * PADS + kc]);
            a[2] = f2tf(sS[r0 * PADS + kc + 4]);
            a[3] = f2tf(sS[(r0 + 8) * PADS + kc + 4]);
            int key = wk * 16 + kk * 8 + (lane & 3);
            #pragma unroll
            for (int nt = 0; nt < 4; nt++) {
                int dc = wnv * 32 + nt * 8 + (lane >> 2);
                unsigned b0 = f2tf(sV[key * PADV + dc]);
                unsigned b1 = f2tf(sV[(key + 4) * PADV + dc]);
                mma8(o[nt], a, b0, b1);
            }
        }
        __syncthreads();    // V(c) reads done
        if (c + 1 < NCH) {  // issue V(c+1)
            const float* src = gV + (size_t)(c + 1) * KC * D_;
            #pragma unroll
            for (int j = 0; j < 4; j++) {
                int f = j * NTHREADS + tid;
                int row = f >> 4, c4 = f & 15;
                cpasync16(sKV + row * PADV + c4 * 4, src + row * D_ + c4 * 4);
            }
            CP_COMMIT();
        }
        // attn slab for chunk c: 16 rows x 32 f4, one f4 per thread (overlaps load)
        if (gA) {
            int r = tid >> 5;
            float inv = sInv[r];
            float4 p = reinterpret_cast<const float4*>(sS + (size_t)r * PADS)[c * 32 + lane];
            p.x *= inv; p.y *= inv; p.z *= inv; p.w *= inv;
            reinterpret_cast<float4*>(gA + (size_t)r * S_)[c * 32 + lane] = p;
        }
        if (c + 1 < NCH) { CP_WAIT0(); __syncthreads(); }
    }
    __syncthreads();   // attn reads of sS done; safe to overwrite

    // ---- 8-way k reduction (reuse sS), fold invl, write O ----
    {
        float* red = sS;
        float* base = red + warp * RPART;
        int r0 = lane >> 2;
        #pragma unroll
        for (int nt = 0; nt < 4; nt++) {
            int lc = nt * 8 + 2 * (lane & 3);
            *reinterpret_cast<float2*>(&base[r0 * RSTR + lc])       = make_float2(o[nt][0], o[nt][1]);
            *reinterpret_cast<float2*>(&base[(r0 + 8) * RSTR + lc]) = make_float2(o[nt][2], o[nt][3]);
        }
    }
    __syncthreads();
    {
        const float* red = sS;
        int r  = tid >> 5;
        int cc = lane * 2;
        int wv = cc >> 5, lc = cc & 31;
        float2 s = make_float2(0.f, 0.f);
        #pragma unroll
        for (int k = 0; k < 8; k++) {
            float2 t = *reinterpret_cast<const float2*>(
                &red[(size_t)(wv * 8 + k) * RPART + r * RSTR + lc]);
            s.x += t.x; s.y += t.y;
        }
        float inv = sInv[r];
        *reinterpret_cast<float2*>(&gO[(size_t)r * D_ + cc]) = make_float2(s.x * inv, s.y * inv);
    }
}

extern "C" void kernel_launch(void* const* d_in, const int* in_sizes, int n_in,
                              void* d_out, int out_size)
{
    const float* q    = (const float*)d_in[0];
    const float* k    = (const float*)d_in[1];
    const float* v    = (const float*)d_in[2];
    const int*   mask = (const int*)d_in[3];
    float* out = (float*)d_out;

    const size_t out_elems  = (size_t)BH_ * S_ * D_;   //  4,194,304
    const size_t attn_elems = (size_t)BH_ * S_ * S_;   // 67,108,864
    float* attn = ((size_t)out_size >= out_elems + attn_elems) ? (out + out_elems) : nullptr;

    cudaFuncSetAttribute(attn_kernel, cudaFuncAttributeMaxDynamicSharedMemorySize, SMEM_BYTES);

    dim3 grid(S_ / QT, BH_);
    attn_kernel<<<grid, NTHREADS, SMEM_BYTES>>>(q, k, v, mask, out, attn);
}